// round 13
// baseline (speedup 1.0000x reference)
#include <cuda_runtime.h>
#include <cuda_fp16.h>
#include <math.h>

// Problem constants
#define BB 8
#define NN 4096
#define CC 768
#define HH 8
#define DD 96
#define C3 2304
#define BH (BB*HH)
#define SPLITS 8
#define K3 1536   // A' row length: [hi(768)|lo(768)]
#define MTOT (BB*NN)

// Scratch (device globals — allocation-free kernel_launch)
__device__ float g_q[BB*HH*DD*NN];     // [b][h][d][n]
__device__ float g_k[BB*HH*DD*NN];
__device__ float g_v[BB*HH*DD*NN];
__device__ float g_sq[2*BH*DD];        // sumsq: [0]=q rows, [1]=k rows
__device__ float g_part[SPLITS*BH*DD*DD];
__device__ float g_attn[BH*DD*DD];

// fp16 operands. A' m-major [m][hi|lo]; W single-copy fp16 [k(768)][n]
__device__ __half g_xs[(size_t)MTOT*K3];
__device__ __half g_ys[(size_t)MTOT*K3];
__device__ __half g_ws[(size_t)CC*C3];
__device__ __half g_wps[(size_t)CC*CC];

// ---------------------------------------------------------------------------
// MMA / ldmatrix / cp.async helpers
// ---------------------------------------------------------------------------
__device__ __forceinline__ void mma16816(float* c, const unsigned* a, const unsigned* b) {
    asm volatile(
        "mma.sync.aligned.m16n8k16.row.col.f32.f16.f16.f32 "
        "{%0,%1,%2,%3}, {%4,%5,%6,%7}, {%8,%9}, {%0,%1,%2,%3};"
        : "+f"(c[0]), "+f"(c[1]), "+f"(c[2]), "+f"(c[3])
        : "r"(a[0]), "r"(a[1]), "r"(a[2]), "r"(a[3]), "r"(b[0]), "r"(b[1]));
}
__device__ __forceinline__ void ldsm_x4(unsigned* r, const void* p) {
    unsigned addr = (unsigned)__cvta_generic_to_shared(p);
    asm volatile("ldmatrix.sync.aligned.m8n8.x4.shared.b16 {%0,%1,%2,%3}, [%4];"
        : "=r"(r[0]), "=r"(r[1]), "=r"(r[2]), "=r"(r[3]) : "r"(addr));
}
__device__ __forceinline__ void ldsm_x4_t(unsigned* r, const void* p) {
    unsigned addr = (unsigned)__cvta_generic_to_shared(p);
    asm volatile("ldmatrix.sync.aligned.m8n8.x4.trans.shared.b16 {%0,%1,%2,%3}, [%4];"
        : "=r"(r[0]), "=r"(r[1]), "=r"(r[2]), "=r"(r[3]) : "r"(addr));
}
__device__ __forceinline__ void cp16(const void* smem_dst, const void* gsrc) {
    unsigned d = (unsigned)__cvta_generic_to_shared(smem_dst);
    asm volatile("cp.async.cg.shared.global [%0], [%1], 16;" :: "r"(d), "l"(gsrc));
}
#define CP_COMMIT() asm volatile("cp.async.commit_group;" ::: "memory")
#define CP_WAIT1()  asm volatile("cp.async.wait_group 1;" ::: "memory")

__device__ __forceinline__ void split_hl(float v, __half& hi, __half& lo) {
    hi = __float2half(v);
    lo = __float2half(v - __half2float(hi));
}
__device__ __forceinline__ void split4(float4 v, __half* h, __half* l) {
    split_hl(v.x, h[0], l[0]); split_hl(v.y, h[1], l[1]);
    split_hl(v.z, h[2], l[2]); split_hl(v.w, h[3], l[3]);
}

// ---------------------------------------------------------------------------
// Split kernels
// ---------------------------------------------------------------------------
__global__ __launch_bounds__(256) void split_x_kernel(const float* __restrict__ x)
{
    int idx = blockIdx.x * 256 + threadIdx.x;
    int m = idx / (CC / 4);
    int k4 = (idx - m * (CC / 4)) * 4;
    float4 v = *(const float4*)&x[(size_t)m * CC + k4];
    __half hi[4], lo[4];
    split4(v, hi, lo);
    __half* base = g_xs + (size_t)m * K3 + k4;
    *(uint2*)(base)      = *(uint2*)hi;
    *(uint2*)(base + CC) = *(uint2*)lo;
}

__global__ __launch_bounds__(256) void split_wqkv_kernel(const float* __restrict__ w)
{
    int idx = blockIdx.x * 256 + threadIdx.x;
    int k = idx / (C3 / 4);
    int n4 = (idx - k * (C3 / 4)) * 4;
    float4 v = *(const float4*)&w[(size_t)k * C3 + n4];
    __half hi[4];
    hi[0] = __float2half(v.x); hi[1] = __float2half(v.y);
    hi[2] = __float2half(v.z); hi[3] = __float2half(v.w);
    *(uint2*)&g_ws[(size_t)k * C3 + n4] = *(uint2*)hi;
}

__global__ __launch_bounds__(256) void split_wproj_kernel(const float* __restrict__ w)
{
    int idx = blockIdx.x * 256 + threadIdx.x;
    int k = idx / (CC / 4);
    int n4 = (idx - k * (CC / 4)) * 4;
    float4 v = *(const float4*)&w[(size_t)k * CC + n4];
    __half hi[4];
    hi[0] = __float2half(v.x); hi[1] = __float2half(v.y);
    hi[2] = __float2half(v.z); hi[3] = __float2half(v.w);
    *(uint2*)&g_wps[(size_t)k * CC + n4] = *(uint2*)hi;
}

__global__ __launch_bounds__(256) void zero_sq_kernel()
{
    int i = blockIdx.x * 256 + threadIdx.x;
    if (i < 2 * BH * DD) g_sq[i] = 0.f;
}

// ---------------------------------------------------------------------------
// fp16 MMA GEMM with B-fragment reuse: C = A_hi*B + A_lo*B, K depth 768.
// BM=128, BN=128, BK=32, 24 chunks. 128 thr = 4 warps (2x2), 64x64 warp tile.
// 3-stage cp.async pipeline (dyn SMEM). Each B fragment feeds 2 MMAs.
// Stage (halves): A_hi 128x40=5120 | A_lo 5120 | B 32x136=4352 -> 14592.
// ---------------------------------------------------------------------------
#define STG_H 14592
#define AL_OFF 5120
#define B_OFF 10240
#define NSTG 3

__global__ __launch_bounds__(128, 2) void mma_gemm_kernel(
    int Ncols, int mode, const float* __restrict__ bias, float* __restrict__ out)
{
    extern __shared__ __align__(16) __half smp[];
    const __half* __restrict__ A  = mode ? g_ys  : g_xs;
    const __half* __restrict__ Bm = mode ? g_wps : g_ws;

    const int tid = threadIdx.x;
    const int wid = tid >> 5, lane = tid & 31;
    const int rowBase = blockIdx.y * 128;
    const int colBase = blockIdx.x * 128;
    const int warpM = (wid & 1) * 64;
    const int warpN = (wid >> 1) * 64;

    float acc[4][8][4] = {};

    const int ar = tid >> 2, ac = (tid & 3) * 8;      // A: 4 passes (+32 rows)
    const int br = tid >> 4, bc2 = (tid & 15) * 8;    // B: 4 passes (+8 rows)

    const __half* aptr = A  + (size_t)(rowBase + ar) * K3 + ac;   // hi; +CC = lo
    const __half* bptr = Bm + (size_t)br * Ncols + colBase + bc2;

    const int NT = CC / 32;   // 24

    // prologue: stages 0,1
#pragma unroll
    for (int s = 0; s < 2; s++) {
        __half (*Ah)[40]  = (__half(*)[40]) (smp + s * STG_H);
        __half (*Al)[40]  = (__half(*)[40]) (smp + s * STG_H + AL_OFF);
        __half (*Bs)[136] = (__half(*)[136])(smp + s * STG_H + B_OFF);
        const int k0 = s * 32;
#pragma unroll
        for (int p = 0; p < 4; p++) {
            cp16(&Ah[ar + p * 32][ac], aptr + (size_t)p * 32 * K3 + k0);
            cp16(&Al[ar + p * 32][ac], aptr + (size_t)p * 32 * K3 + k0 + CC);
        }
#pragma unroll
        for (int p = 0; p < 4; p++)
            cp16(&Bs[br + p * 8][bc2], bptr + ((size_t)k0 + p * 8) * Ncols);
        CP_COMMIT();
    }

    for (int t = 0; t < NT; t++) {
        CP_WAIT1();
        __syncthreads();

        if (t + 2 < NT) {
            const int s = (t + 2) % NSTG;
            __half (*Ahn)[40]  = (__half(*)[40]) (smp + s * STG_H);
            __half (*Aln)[40]  = (__half(*)[40]) (smp + s * STG_H + AL_OFF);
            __half (*Bsn)[136] = (__half(*)[136])(smp + s * STG_H + B_OFF);
            const int k0 = (t + 2) * 32;
#pragma unroll
            for (int p = 0; p < 4; p++) {
                cp16(&Ahn[ar + p * 32][ac], aptr + (size_t)p * 32 * K3 + k0);
                cp16(&Aln[ar + p * 32][ac], aptr + (size_t)p * 32 * K3 + k0 + CC);
            }
#pragma unroll
            for (int p = 0; p < 4; p++)
                cp16(&Bsn[br + p * 8][bc2], bptr + ((size_t)k0 + p * 8) * Ncols);
        }
        CP_COMMIT();           // exactly one group per iteration

        const int buf = t % NSTG;
        __half (*Ah)[40]  = (__half(*)[40]) (smp + buf * STG_H);
        __half (*Al)[40]  = (__half(*)[40]) (smp + buf * STG_H + AL_OFF);
        __half (*Bs)[136] = (__half(*)[136])(smp + buf * STG_H + B_OFF);

#pragma unroll
        for (int ks = 0; ks < 2; ks++) {
            unsigned bf[8][2];
#pragma unroll
            for (int g = 0; g < 4; g++) {
                unsigned r[4];
                ldsm_x4_t(r, &Bs[ks * 16 + ((lane >> 3) & 1) * 8 + (lane & 7)]
                             [warpN + g * 16 + (lane >> 4) * 8]);
                bf[2 * g][0] = r[0]; bf[2 * g][1] = r[1];
                bf[2 * g + 1][0] = r[2]; bf[2 * g + 1][1] = r[3];
            }
            unsigned afh[4][4], afl[4][4];
#pragma unroll
            for (int im = 0; im < 4; im++) {
                ldsm_x4(afh[im], &Ah[warpM + im * 16 + (lane & 15)]
                                    [ks * 16 + (lane >> 4) * 8]);
                ldsm_x4(afl[im], &Al[warpM + im * 16 + (lane & 15)]
                                    [ks * 16 + (lane >> 4) * 8]);
            }
#pragma unroll
            for (int im = 0; im < 4; im++)
#pragma unroll
                for (int jn = 0; jn < 8; jn++) {
                    mma16816(acc[im][jn], afh[im], bf[jn]);
                    mma16816(acc[im][jn], afl[im], bf[jn]);
                }
        }
    }

    // Epilogue
#pragma unroll
    for (int im = 0; im < 4; im++) {
#pragma unroll
        for (int jn = 0; jn < 8; jn++) {
#pragma unroll
            for (int q = 0; q < 4; q++) {
                int m = warpM + im * 16 + (lane >> 2) + (q >> 1) * 8;
                int n = warpN + jn * 8 + (lane & 3) * 2 + (q & 1);
                float val = acc[im][jn][q];
                int row = rowBase + m;
                int col = colBase + n;
                if (mode == 0) {
                    int b = row >> 12;
                    int nn2 = row & 4095;
                    int h = col / 288;
                    int rem = col - h * 288;
                    int d = rem / 3;
                    int s = rem - d * 3;
                    float* dst = (s == 0) ? g_q : (s == 1) ? g_k : g_v;
                    dst[((b * HH + h) * DD + d) * NN + nn2] = val;
                } else {
                    out[(size_t)row * CC + col] = val + bias[col];
                }
            }
        }
    }
}

// ---------------------------------------------------------------------------
// attn_part (tensor MMA + fused sumsq)
// ---------------------------------------------------------------------------
__global__ __launch_bounds__(128) void attn_part_kernel()
{
    __shared__ __align__(16) __half Qs[2][96][40];
    __shared__ __align__(16) __half Ks[2][96][40];
    __shared__ float sqs[2][96];
    const int tid = threadIdx.x;
    const int wid = tid >> 5, lane = tid & 31;
    const int bh = blockIdx.x;
    const int n0 = blockIdx.y * (NN / SPLITS);
    const float* qp = g_q + (size_t)bh * DD * NN;
    const float* kp = g_k + (size_t)bh * DD * NN;
    const int warpM = (wid & 1) * 48, warpN = (wid >> 1) * 48;

    if (tid < 96) { sqs[0][tid] = 0.f; sqs[1][tid] = 0.f; }

    float acc[3][6][4] = {};
    float sq_q[6] = {}, sq_k[6] = {};

    for (int nc = 0; nc < NN / SPLITS; nc += 32) {
        if (nc) __syncthreads();
#pragma unroll
        for (int p = 0; p < 6; p++) {
            int idx = p * 128 + tid;
            int r = idx >> 3, c4 = (idx & 7) * 4;
            float4 qv = *(const float4*)&qp[(size_t)r * NN + n0 + nc + c4];
            float4 kv = *(const float4*)&kp[(size_t)r * NN + n0 + nc + c4];
            sq_q[p] = fmaf(qv.x, qv.x, fmaf(qv.y, qv.y, fmaf(qv.z, qv.z, fmaf(qv.w, qv.w, sq_q[p]))));
            sq_k[p] = fmaf(kv.x, kv.x, fmaf(kv.y, kv.y, fmaf(kv.z, kv.z, fmaf(kv.w, kv.w, sq_k[p]))));
            __half qh[4], ql[4], kh[4], kl[4];
            split4(qv, qh, ql); split4(kv, kh, kl);
            *(uint2*)&Qs[0][r][c4] = *(uint2*)qh;
            *(uint2*)&Qs[1][r][c4] = *(uint2*)ql;
            *(uint2*)&Ks[0][r][c4] = *(uint2*)kh;
            *(uint2*)&Ks[1][r][c4] = *(uint2*)kl;
        }
        __syncthreads();
#pragma unroll
        for (int term = 0; term < 3; term++) {
            const __half (*Aq)[40] = (term == 1) ? Qs[1] : Qs[0];
            const __half (*Bk)[40] = (term == 2) ? Ks[1] : Ks[0];
#pragma unroll
            for (int ks = 0; ks < 2; ks++) {
                unsigned af[3][4];
#pragma unroll
                for (int im = 0; im < 3; im++)
                    ldsm_x4(af[im], &Aq[warpM + im * 16 + (lane & 15)]
                                       [ks * 16 + (lane >> 4) * 8]);
                unsigned bf[6][2];
#pragma unroll
                for (int jg = 0; jg < 3; jg++) {
                    unsigned r4[4];
                    ldsm_x4(r4, &Bk[warpN + jg * 16 + (lane & 15)]
                                   [ks * 16 + (lane >> 4) * 8]);
                    bf[2 * jg][0] = r4[0]; bf[2 * jg][1] = r4[2];
                    bf[2 * jg + 1][0] = r4[1]; bf[2 * jg + 1][1] = r4[3];
                }
#pragma unroll
                for (int im = 0; im < 3; im++)
#pragma unroll
                    for (int jn = 0; jn < 6; jn++)
                        mma16816(acc[im][jn], af[im], bf[jn]);
            }
        }
    }

#pragma unroll
    for (int p = 0; p < 6; p++) {
        int r = (p * 128 + tid) >> 3;
        atomicAdd(&sqs[0][r], sq_q[p]);
        atomicAdd(&sqs[1][r], sq_k[p]);
    }
    __syncthreads();
    if (tid < 96) {
        atomicAdd(&g_sq[bh * DD + tid], sqs[0][tid]);
        atomicAdd(&g_sq[BH * DD + bh * DD + tid], sqs[1][tid]);
    }

    float* dst = g_part + ((size_t)blockIdx.y * BH + bh) * DD * DD;
#pragma unroll
    for (int im = 0; im < 3; im++)
#pragma unroll
        for (int jn = 0; jn < 6; jn++)
#pragma unroll
            for (int q = 0; q < 4; q++) {
                int row = warpM + im * 16 + (lane >> 2) + (q >> 1) * 8;
                int col = warpN + jn * 8 + (lane & 3) * 2 + (q & 1);
                dst[row * DD + col] = acc[im][jn][q];
            }
}

// ---------------------------------------------------------------------------
// softmax
// ---------------------------------------------------------------------------
__global__ __launch_bounds__(128) void softmax_kernel(const float* __restrict__ temp)
{
    const int bhd = blockIdx.x;
    const int bh = bhd / DD;
    const int d  = bhd - bh * DD;
    const int h  = bh & (HH - 1);
    const int e  = threadIdx.x;

    float raw = 0.f;
    float val = -1e30f;
    if (e < DD) {
        float s = 0.f;
#pragma unroll
        for (int sp = 0; sp < SPLITS; sp++)
            s += g_part[(((size_t)sp * BH + bh) * DD + d) * DD + e];
        raw = s * rsqrtf(g_sq[bh * DD + d]) * rsqrtf(g_sq[BH * DD + bh * DD + e]) * temp[h];
        val = raw;
    }

    __shared__ float red[128];
    red[e] = val;
    __syncthreads();
#pragma unroll
    for (int off = 64; off >= 1; off >>= 1) {
        if (e < off) red[e] = fmaxf(red[e], red[e + off]);
        __syncthreads();
    }
    float m = red[0];
    __syncthreads();

    float ex = (e < DD) ? expf(raw - m) : 0.f;
    red[e] = ex;
    __syncthreads();
#pragma unroll
    for (int off = 64; off >= 1; off >>= 1) {
        if (e < off) red[e] += red[e + off];
        __syncthreads();
    }
    float sum = red[0];

    if (e < DD)
        g_attn[((size_t)bh * DD + d) * DD + e] = ex / sum;
}

// ---------------------------------------------------------------------------
// av (tensor MMA, transposed output into g_ys)
// ---------------------------------------------------------------------------
__global__ __launch_bounds__(128) void av_kernel()
{
    __shared__ __align__(16) __half Ah[2][96][104];
    __shared__ __align__(16) __half Vs[2][16][136];
    const int tid = threadIdx.x;
    const int wid = tid >> 5, lane = tid & 31;
    const int bh = blockIdx.x;
    const int n0 = blockIdx.y * 128;
    const int b = bh >> 3, h = bh & 7;
    const float* ap = g_attn + (size_t)bh * DD * DD;
    const float* vp = g_v + (size_t)bh * DD * NN;
    const int warpMn = (wid & 1) * 64;
    const int warpNd = (wid >> 1) * 48;

    float acc[4][6][4] = {};

#pragma unroll
    for (int p = 0; p < 18; p++) {
        int idx = p * 128 + tid;
        int r = idx / 24, c4 = (idx % 24) * 4;
        float4 v = *(const float4*)&ap[r * DD + c4];
        __half hh[4], ll[4];
        split4(v, hh, ll);
        *(uint2*)&Ah[0][r][c4] = *(uint2*)hh;
        *(uint2*)&Ah[1][r][c4] = *(uint2*)ll;
    }

    for (int ec = 0; ec < DD; ec += 16) {
        __syncthreads();
#pragma unroll
        for (int p = 0; p < 4; p++) {
            int idx = p * 128 + tid;
            int r = idx >> 5, c4 = (idx & 31) * 4;
            float4 vv = *(const float4*)&vp[(size_t)(ec + r) * NN + n0 + c4];
            __half hh[4], ll[4];
            split4(vv, hh, ll);
            *(uint2*)&Vs[0][r][c4] = *(uint2*)hh;
            *(uint2*)&Vs[1][r][c4] = *(uint2*)ll;
        }
        __syncthreads();
#pragma unroll
        for (int term = 0; term < 3; term++) {
            const __half (*Aa)[104] = (term == 1) ? Ah[1] : Ah[0];
            const __half (*Vv)[136] = (term == 2) ? Vs[1] : Vs[0];
            unsigned af[4][4];
#pragma unroll
            for (int im = 0; im < 4; im++) {
                unsigned r4[4];
                ldsm_x4_t(r4, &Vv[((lane >> 3) & 1) * 8 + (lane & 7)]
                              [warpMn + im * 16 + (lane >> 4) * 8]);
                af[im][0] = r4[0]; af[im][1] = r4[2];
                af[im][2] = r4[1]; af[im][3] = r4[3];
            }
            unsigned bf[6][2];
#pragma unroll
            for (int jg = 0; jg < 3; jg++) {
                unsigned r4[4];
                ldsm_x4(r4, &Aa[warpNd + jg * 16 + (lane & 15)]
                               [ec + (lane >> 4) * 8]);
                bf[2 * jg][0] = r4[0]; bf[2 * jg][1] = r4[2];
                bf[2 * jg + 1][0] = r4[1]; bf[2 * jg + 1][1] = r4[3];
            }
#pragma unroll
            for (int im = 0; im < 4; im++)
#pragma unroll
                for (int jn = 0; jn < 6; jn++)
                    mma16816(acc[im][jn], af[im], bf[jn]);
        }
    }

    __half* ybase = g_ys + ((size_t)b * NN + n0) * K3 + h * DD;
#pragma unroll
    for (int im = 0; im < 4; im++) {
#pragma unroll
        for (int jn = 0; jn < 6; jn++) {
            int rown0 = warpMn + im * 16 + (lane >> 2);
            int cold  = warpNd + jn * 8 + (lane & 3) * 2;
#pragma unroll
            for (int rr = 0; rr < 2; rr++) {
                int rown = rown0 + rr * 8;
                float v0 = acc[im][jn][rr * 2 + 0];
                float v1 = acc[im][jn][rr * 2 + 1];
                __half h0, l0, h1, l1;
                split_hl(v0, h0, l0); split_hl(v1, h1, l1);
                __half* pp = ybase + (size_t)rown * K3 + cold;
                *(__half2*)pp        = __halves2half2(h0, h1);
                *(__half2*)(pp + CC) = __halves2half2(l0, l1);
            }
        }
    }
}

// ---------------------------------------------------------------------------
extern "C" void kernel_launch(void* const* d_in, const int* in_sizes, int n_in,
                              void* d_out, int out_size)
{
    const float* x      = (const float*)d_in[0];
    const float* w_qkv  = (const float*)d_in[1];
    const float* w_proj = (const float*)d_in[2];
    const float* b_proj = (const float*)d_in[3];
    const float* temp   = (const float*)d_in[4];
    float* out = (float*)d_out;

    const int gemm_smem = NSTG * STG_H * (int)sizeof(__half);   // 87552 B
    cudaFuncSetAttribute(mma_gemm_kernel,
                         cudaFuncAttributeMaxDynamicSharedMemorySize, gemm_smem);

    split_x_kernel<<<(MTOT * CC / 4) / 256, 256>>>(x);
    split_wqkv_kernel<<<(CC * C3 / 4) / 256, 256>>>(w_qkv);
    split_wproj_kernel<<<(CC * CC / 4) / 256, 256>>>(w_proj);
    zero_sq_kernel<<<(2 * BH * DD + 255) / 256, 256>>>();

    // GEMM1: scatter q/k/v
    mma_gemm_kernel<<<dim3(C3 / 128, MTOT / 128), 128, gemm_smem>>>(C3, 0, nullptr, nullptr);

    attn_part_kernel<<<dim3(BH, SPLITS), 128>>>();
    softmax_kernel<<<BH * DD, 128>>>(temp);
    av_kernel<<<dim3(BH, NN / 128), 128>>>();

    // GEMM2: out = y @ W_proj + bias
    mma_gemm_kernel<<<dim3(CC / 128, MTOT / 128), 128, gemm_smem>>>(CC, 1, b_proj, out);
}

// round 14
// speedup vs baseline: 1.1044x; 1.1044x over previous
#include <cuda_runtime.h>
#include <cuda_fp16.h>
#include <math.h>

// Problem constants
#define BB 8
#define NN 4096
#define CC 768
#define HH 8
#define DD 96
#define C3 2304
#define BH (BB*HH)
#define SPLITS 8
#define K3 1536   // A' row length: [hi(768)|lo(768)]
#define MTOT (BB*NN)

// Scratch (device globals — allocation-free kernel_launch)
__device__ float g_q[BB*HH*DD*NN];     // [b][h][d][n]
__device__ float g_k[BB*HH*DD*NN];
__device__ float g_v[BB*HH*DD*NN];
__device__ float g_sq[2*BH*DD];        // sumsq: [0]=q rows, [1]=k rows
__device__ float g_part[SPLITS*BH*DD*DD];
__device__ float g_attn[BH*DD*DD];

// fp16 operands. A' m-major [m][hi|lo]; W single-copy fp16 [k(768)][n]
__device__ __half g_xs[(size_t)MTOT*K3];
__device__ __half g_ys[(size_t)MTOT*K3];    // GEMM2 A' (written by av directly)
__device__ __half g_ws[(size_t)CC*C3];
__device__ __half g_wps[(size_t)CC*CC];

// ---------------------------------------------------------------------------
// MMA / ldmatrix / cp.async helpers
// ---------------------------------------------------------------------------
__device__ __forceinline__ void mma16816(float* c, const unsigned* a, const unsigned* b) {
    asm volatile(
        "mma.sync.aligned.m16n8k16.row.col.f32.f16.f16.f32 "
        "{%0,%1,%2,%3}, {%4,%5,%6,%7}, {%8,%9}, {%0,%1,%2,%3};"
        : "+f"(c[0]), "+f"(c[1]), "+f"(c[2]), "+f"(c[3])
        : "r"(a[0]), "r"(a[1]), "r"(a[2]), "r"(a[3]), "r"(b[0]), "r"(b[1]));
}
__device__ __forceinline__ void ldsm_x4(unsigned* r, const void* p) {
    unsigned addr = (unsigned)__cvta_generic_to_shared(p);
    asm volatile("ldmatrix.sync.aligned.m8n8.x4.shared.b16 {%0,%1,%2,%3}, [%4];"
        : "=r"(r[0]), "=r"(r[1]), "=r"(r[2]), "=r"(r[3]) : "r"(addr));
}
__device__ __forceinline__ void ldsm_x4_t(unsigned* r, const void* p) {
    unsigned addr = (unsigned)__cvta_generic_to_shared(p);
    asm volatile("ldmatrix.sync.aligned.m8n8.x4.trans.shared.b16 {%0,%1,%2,%3}, [%4];"
        : "=r"(r[0]), "=r"(r[1]), "=r"(r[2]), "=r"(r[3]) : "r"(addr));
}
__device__ __forceinline__ void cp16(const void* smem_dst, const void* gsrc) {
    unsigned d = (unsigned)__cvta_generic_to_shared(smem_dst);
    asm volatile("cp.async.cg.shared.global [%0], [%1], 16;" :: "r"(d), "l"(gsrc));
}
#define CP_COMMIT() asm volatile("cp.async.commit_group;" ::: "memory")
#define CP_WAIT2()  asm volatile("cp.async.wait_group 2;" ::: "memory")

__device__ __forceinline__ void split_hl(float v, __half& hi, __half& lo) {
    hi = __float2half(v);
    lo = __float2half(v - __half2float(hi));
}
__device__ __forceinline__ void split4(float4 v, __half* h, __half* l) {
    split_hl(v.x, h[0], l[0]); split_hl(v.y, h[1], l[1]);
    split_hl(v.z, h[2], l[2]); split_hl(v.w, h[3], l[3]);
}

// ---------------------------------------------------------------------------
// Split kernels: A rows m-major [hi|lo]; W single-copy fp16
// ---------------------------------------------------------------------------
__global__ __launch_bounds__(256) void split_x_kernel(const float* __restrict__ x)
{
    int idx = blockIdx.x * 256 + threadIdx.x;
    int m = idx / (CC / 4);
    int k4 = (idx - m * (CC / 4)) * 4;
    float4 v = *(const float4*)&x[(size_t)m * CC + k4];
    __half hi[4], lo[4];
    split4(v, hi, lo);
    __half* base = g_xs + (size_t)m * K3 + k4;
    *(uint2*)(base)      = *(uint2*)hi;
    *(uint2*)(base + CC) = *(uint2*)lo;
}

__global__ __launch_bounds__(256) void split_wqkv_kernel(const float* __restrict__ w)
{
    int idx = blockIdx.x * 256 + threadIdx.x;
    int k = idx / (C3 / 4);
    int n4 = (idx - k * (C3 / 4)) * 4;
    float4 v = *(const float4*)&w[(size_t)k * C3 + n4];
    __half hi[4];
    hi[0] = __float2half(v.x); hi[1] = __float2half(v.y);
    hi[2] = __float2half(v.z); hi[3] = __float2half(v.w);
    *(uint2*)&g_ws[(size_t)k * C3 + n4] = *(uint2*)hi;
}

__global__ __launch_bounds__(256) void split_wproj_kernel(const float* __restrict__ w)
{
    int idx = blockIdx.x * 256 + threadIdx.x;
    int k = idx / (CC / 4);
    int n4 = (idx - k * (CC / 4)) * 4;
    float4 v = *(const float4*)&w[(size_t)k * CC + n4];
    __half hi[4];
    hi[0] = __float2half(v.x); hi[1] = __float2half(v.y);
    hi[2] = __float2half(v.z); hi[3] = __float2half(v.w);
    *(uint2*)&g_wps[(size_t)k * CC + n4] = *(uint2*)hi;
}

__global__ __launch_bounds__(256) void zero_sq_kernel()
{
    int i = blockIdx.x * 256 + threadIdx.x;
    if (i < 2 * BH * DD) g_sq[i] = 0.f;
}

// ---------------------------------------------------------------------------
// fp16 MMA GEMM (R12 structure): BM=128, BN=128, BK=32. 128 thr = 4 warps
// (2x2), 64x64 warp tile. 4-stage cp.async pipeline, 2 CTAs/SM.
// B row index wraps mod 768 (single weight copy; A' = [hi|lo] drives 2 passes).
// Stage (halves): As 128x40 = 5120, Bs 32x136 = 4352 -> 9472/stage.
// ---------------------------------------------------------------------------
#define STG_H 9472
#define NSTG 4

__global__ __launch_bounds__(128, 2) void mma_gemm_kernel(
    int Ncols, int mode, const float* __restrict__ bias, float* __restrict__ out)
{
    extern __shared__ __align__(16) __half smp[];
    const __half* __restrict__ A  = mode ? g_ys  : g_xs;
    const __half* __restrict__ Bm = mode ? g_wps : g_ws;

    const int tid = threadIdx.x;
    const int wid = tid >> 5, lane = tid & 31;
    const int rowBase = blockIdx.y * 128;
    const int colBase = blockIdx.x * 128;
    const int warpM = (wid & 1) * 64;
    const int warpN = (wid >> 1) * 64;

    float acc[4][8][4] = {};

    const int ar = tid >> 2, ac = (tid & 3) * 8;      // A: 4 passes (+32 rows)
    const int br = tid >> 4, bc2 = (tid & 15) * 8;    // B: 4 passes (+8 rows)

    const __half* aptr = A  + (size_t)(rowBase + ar) * K3 + ac;
    const __half* bptr = Bm + (size_t)br * Ncols + colBase + bc2;

    const int NT = K3 / 32;   // 48; B wraps at chunk 24

    // prologue: stages 0..2 (k0 < CC, no wrap)
#pragma unroll
    for (int s = 0; s < 3; s++) {
        __half (*As)[40]  = (__half(*)[40]) (smp + s * STG_H);
        __half (*Bs)[136] = (__half(*)[136])(smp + s * STG_H + 5120);
        const int k0 = s * 32;
#pragma unroll
        for (int p = 0; p < 4; p++)
            cp16(&As[ar + p * 32][ac], aptr + (size_t)p * 32 * K3 + k0);
#pragma unroll
        for (int p = 0; p < 4; p++)
            cp16(&Bs[br + p * 8][bc2], bptr + ((size_t)k0 + p * 8) * Ncols);
        CP_COMMIT();
    }

    for (int t = 0; t < NT; t++) {
        CP_WAIT2();            // stage t retired (two newer groups may be pending)
        __syncthreads();

        if (t + 3 < NT) {      // issue stage t+3 into buffer (t+3)%4
            const int s = (t + 3) % NSTG;
            __half (*Asn)[40]  = (__half(*)[40]) (smp + s * STG_H);
            __half (*Bsn)[136] = (__half(*)[136])(smp + s * STG_H + 5120);
            const int k0 = (t + 3) * 32;
            const int kb = (k0 >= CC) ? (k0 - CC) : k0;   // B single copy wrap
#pragma unroll
            for (int p = 0; p < 4; p++)
                cp16(&Asn[ar + p * 32][ac], aptr + (size_t)p * 32 * K3 + k0);
#pragma unroll
            for (int p = 0; p < 4; p++)
                cp16(&Bsn[br + p * 8][bc2], bptr + ((size_t)kb + p * 8) * Ncols);
        }
        CP_COMMIT();           // exactly one group per iteration (empty at tail)

        const int buf = t % NSTG;
        __half (*As)[40]  = (__half(*)[40]) (smp + buf * STG_H);
        __half (*Bs)[136] = (__half(*)[136])(smp + buf * STG_H + 5120);

#pragma unroll
        for (int ks = 0; ks < 2; ks++) {
            unsigned af[4][4];
#pragma unroll
            for (int im = 0; im < 4; im++)
                ldsm_x4(af[im], &As[warpM + im * 16 + (lane & 15)]
                                   [ks * 16 + (lane >> 4) * 8]);
            unsigned bf[8][2];
#pragma unroll
            for (int g = 0; g < 4; g++) {
                unsigned r[4];
                ldsm_x4_t(r, &Bs[ks * 16 + ((lane >> 3) & 1) * 8 + (lane & 7)]
                             [warpN + g * 16 + (lane >> 4) * 8]);
                bf[2 * g][0] = r[0]; bf[2 * g][1] = r[1];
                bf[2 * g + 1][0] = r[2]; bf[2 * g + 1][1] = r[3];
            }
#pragma unroll
            for (int im = 0; im < 4; im++)
#pragma unroll
                for (int jn = 0; jn < 8; jn++)
                    mma16816(acc[im][jn], af[im], bf[jn]);
        }
    }

    // Epilogue
#pragma unroll
    for (int im = 0; im < 4; im++) {
#pragma unroll
        for (int jn = 0; jn < 8; jn++) {
#pragma unroll
            for (int q = 0; q < 4; q++) {
                int m = warpM + im * 16 + (lane >> 2) + (q >> 1) * 8;
                int n = warpN + jn * 8 + (lane & 3) * 2 + (q & 1);
                float val = acc[im][jn][q];
                int row = rowBase + m;
                int col = colBase + n;
                if (mode == 0) {
                    int b = row >> 12;
                    int nn2 = row & 4095;
                    int h = col / 288;
                    int rem = col - h * 288;
                    int d = rem / 3;
                    int s = rem - d * 3;
                    float* dst = (s == 0) ? g_q : (s == 1) ? g_k : g_v;
                    dst[((b * HH + h) * DD + d) * NN + nn2] = val;
                } else {
                    out[(size_t)row * CC + col] = val + bias[col];
                }
            }
        }
    }
}

// ---------------------------------------------------------------------------
// attn_part (tensor MMA + fused sumsq)
// ---------------------------------------------------------------------------
__global__ __launch_bounds__(128) void attn_part_kernel()
{
    __shared__ __align__(16) __half Qs[2][96][40];
    __shared__ __align__(16) __half Ks[2][96][40];
    __shared__ float sqs[2][96];
    const int tid = threadIdx.x;
    const int wid = tid >> 5, lane = tid & 31;
    const int bh = blockIdx.x;
    const int n0 = blockIdx.y * (NN / SPLITS);
    const float* qp = g_q + (size_t)bh * DD * NN;
    const float* kp = g_k + (size_t)bh * DD * NN;
    const int warpM = (wid & 1) * 48, warpN = (wid >> 1) * 48;

    if (tid < 96) { sqs[0][tid] = 0.f; sqs[1][tid] = 0.f; }

    float acc[3][6][4] = {};
    float sq_q[6] = {}, sq_k[6] = {};

    for (int nc = 0; nc < NN / SPLITS; nc += 32) {
        if (nc) __syncthreads();
#pragma unroll
        for (int p = 0; p < 6; p++) {
            int idx = p * 128 + tid;
            int r = idx >> 3, c4 = (idx & 7) * 4;
            float4 qv = *(const float4*)&qp[(size_t)r * NN + n0 + nc + c4];
            float4 kv = *(const float4*)&kp[(size_t)r * NN + n0 + nc + c4];
            sq_q[p] = fmaf(qv.x, qv.x, fmaf(qv.y, qv.y, fmaf(qv.z, qv.z, fmaf(qv.w, qv.w, sq_q[p]))));
            sq_k[p] = fmaf(kv.x, kv.x, fmaf(kv.y, kv.y, fmaf(kv.z, kv.z, fmaf(kv.w, kv.w, sq_k[p]))));
            __half qh[4], ql[4], kh[4], kl[4];
            split4(qv, qh, ql); split4(kv, kh, kl);
            *(uint2*)&Qs[0][r][c4] = *(uint2*)qh;
            *(uint2*)&Qs[1][r][c4] = *(uint2*)ql;
            *(uint2*)&Ks[0][r][c4] = *(uint2*)kh;
            *(uint2*)&Ks[1][r][c4] = *(uint2*)kl;
        }
        __syncthreads();
#pragma unroll
        for (int term = 0; term < 3; term++) {
            const __half (*Aq)[40] = (term == 1) ? Qs[1] : Qs[0];
            const __half (*Bk)[40] = (term == 2) ? Ks[1] : Ks[0];
#pragma unroll
            for (int ks = 0; ks < 2; ks++) {
                unsigned af[3][4];
#pragma unroll
                for (int im = 0; im < 3; im++)
                    ldsm_x4(af[im], &Aq[warpM + im * 16 + (lane & 15)]
                                       [ks * 16 + (lane >> 4) * 8]);
                unsigned bf[6][2];
#pragma unroll
                for (int jg = 0; jg < 3; jg++) {
                    unsigned r4[4];
                    ldsm_x4(r4, &Bk[warpN + jg * 16 + (lane & 15)]
                                   [ks * 16 + (lane >> 4) * 8]);
                    bf[2 * jg][0] = r4[0]; bf[2 * jg][1] = r4[2];
                    bf[2 * jg + 1][0] = r4[1]; bf[2 * jg + 1][1] = r4[3];
                }
#pragma unroll
                for (int im = 0; im < 3; im++)
#pragma unroll
                    for (int jn = 0; jn < 6; jn++)
                        mma16816(acc[im][jn], af[im], bf[jn]);
            }
        }
    }

#pragma unroll
    for (int p = 0; p < 6; p++) {
        int r = (p * 128 + tid) >> 3;
        atomicAdd(&sqs[0][r], sq_q[p]);
        atomicAdd(&sqs[1][r], sq_k[p]);
    }
    __syncthreads();
    if (tid < 96) {
        atomicAdd(&g_sq[bh * DD + tid], sqs[0][tid]);
        atomicAdd(&g_sq[BH * DD + bh * DD + tid], sqs[1][tid]);
    }

    float* dst = g_part + ((size_t)blockIdx.y * BH + bh) * DD * DD;
#pragma unroll
    for (int im = 0; im < 3; im++)
#pragma unroll
        for (int jn = 0; jn < 6; jn++)
#pragma unroll
            for (int q = 0; q < 4; q++) {
                int row = warpM + im * 16 + (lane >> 2) + (q >> 1) * 8;
                int col = warpN + jn * 8 + (lane & 3) * 2 + (q & 1);
                dst[row * DD + col] = acc[im][jn][q];
            }
}

// ---------------------------------------------------------------------------
// softmax: reduce split-K partials, apply rsqrt(sumsq) * temp, softmax over e.
// ---------------------------------------------------------------------------
__global__ __launch_bounds__(128) void softmax_kernel(const float* __restrict__ temp)
{
    const int bhd = blockIdx.x;
    const int bh = bhd / DD;
    const int d  = bhd - bh * DD;
    const int h  = bh & (HH - 1);
    const int e  = threadIdx.x;

    float raw = 0.f;
    float val = -1e30f;
    if (e < DD) {
        float s = 0.f;
#pragma unroll
        for (int sp = 0; sp < SPLITS; sp++)
            s += g_part[(((size_t)sp * BH + bh) * DD + d) * DD + e];
        raw = s * rsqrtf(g_sq[bh * DD + d]) * rsqrtf(g_sq[BH * DD + bh * DD + e]) * temp[h];
        val = raw;
    }

    __shared__ float red[128];
    red[e] = val;
    __syncthreads();
#pragma unroll
    for (int off = 64; off >= 1; off >>= 1) {
        if (e < off) red[e] = fmaxf(red[e], red[e + off]);
        __syncthreads();
    }
    float m = red[0];
    __syncthreads();

    float ex = (e < DD) ? expf(raw - m) : 0.f;
    red[e] = ex;
    __syncthreads();
#pragma unroll
    for (int off = 64; off >= 1; off >>= 1) {
        if (e < off) red[e] += red[e + off];
        __syncthreads();
    }
    float sum = red[0];

    if (e < DD)
        g_attn[((size_t)bh * DD + d) * DD + e] = ex / sum;
}

// ---------------------------------------------------------------------------
// av (tensor MMA, transposed output): C[n][d] = sum_e v[e,n] * attn[d,e],
// written directly into g_ys [b*N+n][h*96+d] as fp16 hi/lo.
// ---------------------------------------------------------------------------
__global__ __launch_bounds__(128) void av_kernel()
{
    __shared__ __align__(16) __half Ah[2][96][104];   // attn [d][e] hi/lo
    __shared__ __align__(16) __half Vs[2][16][136];   // v [e][n] hi/lo
    const int tid = threadIdx.x;
    const int wid = tid >> 5, lane = tid & 31;
    const int bh = blockIdx.x;
    const int n0 = blockIdx.y * 128;
    const int b = bh >> 3, h = bh & 7;
    const float* ap = g_attn + (size_t)bh * DD * DD;
    const float* vp = g_v + (size_t)bh * DD * NN;
    const int warpMn = (wid & 1) * 64;    // n rows
    const int warpNd = (wid >> 1) * 48;   // d cols

    float acc[4][6][4] = {};

#pragma unroll
    for (int p = 0; p < 18; p++) {
        int idx = p * 128 + tid;
        int r = idx / 24, c4 = (idx % 24) * 4;
        float4 v = *(const float4*)&ap[r * DD + c4];
        __half hh[4], ll[4];
        split4(v, hh, ll);
        *(uint2*)&Ah[0][r][c4] = *(uint2*)hh;
        *(uint2*)&Ah[1][r][c4] = *(uint2*)ll;
    }

    for (int ec = 0; ec < DD; ec += 16) {
        __syncthreads();
#pragma unroll
        for (int p = 0; p < 4; p++) {
            int idx = p * 128 + tid;
            int r = idx >> 5, c4 = (idx & 31) * 4;
            float4 vv = *(const float4*)&vp[(size_t)(ec + r) * NN + n0 + c4];
            __half hh[4], ll[4];
            split4(vv, hh, ll);
            *(uint2*)&Vs[0][r][c4] = *(uint2*)hh;
            *(uint2*)&Vs[1][r][c4] = *(uint2*)ll;
        }
        __syncthreads();
#pragma unroll
        for (int term = 0; term < 3; term++) {
            const __half (*Aa)[104] = (term == 1) ? Ah[1] : Ah[0];   // B operand
            const __half (*Vv)[136] = (term == 2) ? Vs[1] : Vs[0];   // A operand
            unsigned af[4][4];
#pragma unroll
            for (int im = 0; im < 4; im++) {
                unsigned r4[4];
                ldsm_x4_t(r4, &Vv[((lane >> 3) & 1) * 8 + (lane & 7)]
                              [warpMn + im * 16 + (lane >> 4) * 8]);
                af[im][0] = r4[0]; af[im][1] = r4[2];
                af[im][2] = r4[1]; af[im][3] = r4[3];
            }
            unsigned bf[6][2];
#pragma unroll
            for (int jg = 0; jg < 3; jg++) {
                unsigned r4[4];
                ldsm_x4(r4, &Aa[warpNd + jg * 16 + (lane & 15)]
                               [ec + (lane >> 4) * 8]);
                bf[2 * jg][0] = r4[0]; bf[2 * jg][1] = r4[2];
                bf[2 * jg + 1][0] = r4[1]; bf[2 * jg + 1][1] = r4[3];
            }
#pragma unroll
            for (int im = 0; im < 4; im++)
#pragma unroll
                for (int jn = 0; jn < 6; jn++)
                    mma16816(acc[im][jn], af[im], bf[jn]);
        }
    }

    __half* ybase = g_ys + ((size_t)b * NN + n0) * K3 + h * DD;
#pragma unroll
    for (int im = 0; im < 4; im++) {
#pragma unroll
        for (int jn = 0; jn < 6; jn++) {
            int rown0 = warpMn + im * 16 + (lane >> 2);
            int cold  = warpNd + jn * 8 + (lane & 3) * 2;
#pragma unroll
            for (int rr = 0; rr < 2; rr++) {
                int rown = rown0 + rr * 8;
                float v0 = acc[im][jn][rr * 2 + 0];
                float v1 = acc[im][jn][rr * 2 + 1];
                __half h0, l0, h1, l1;
                split_hl(v0, h0, l0); split_hl(v1, h1, l1);
                __half* pp = ybase + (size_t)rown * K3 + cold;
                *(__half2*)pp        = __halves2half2(h0, h1);
                *(__half2*)(pp + CC) = __halves2half2(l0, l1);
            }
        }
    }
}

// ---------------------------------------------------------------------------
extern "C" void kernel_launch(void* const* d_in, const int* in_sizes, int n_in,
                              void* d_out, int out_size)
{
    const float* x      = (const float*)d_in[0];
    const float* w_qkv  = (const float*)d_in[1];
    const float* w_proj = (const float*)d_in[2];
    const float* b_proj = (const float*)d_in[3];
    const float* temp   = (const float*)d_in[4];
    float* out = (float*)d_out;

    const int gemm_smem = NSTG * STG_H * (int)sizeof(__half);   // 75776 B
    cudaFuncSetAttribute(mma_gemm_kernel,
                         cudaFuncAttributeMaxDynamicSharedMemorySize, gemm_smem);

    split_x_kernel<<<(MTOT * CC / 4) / 256, 256>>>(x);
    split_wqkv_kernel<<<(CC * C3 / 4) / 256, 256>>>(w_qkv);
    split_wproj_kernel<<<(CC * CC / 4) / 256, 256>>>(w_proj);
    zero_sq_kernel<<<(2 * BH * DD + 255) / 256, 256>>>();

    // GEMM1: scatter q/k/v
    mma_gemm_kernel<<<dim3(C3 / 128, MTOT / 128), 128, gemm_smem>>>(C3, 0, nullptr, nullptr);

    attn_part_kernel<<<dim3(BH, SPLITS), 128>>>();
    softmax_kernel<<<BH * DD, 128>>>(temp);
    av_kernel<<<dim3(BH, NN / 128), 128>>>();

    // GEMM2: out = y @ W_proj + bias
    mma_gemm_kernel<<<dim3(CC / 128, MTOT / 128), 128, gemm_smem>>>(CC, 1, b_proj, out);
}